// round 13
// baseline (speedup 1.0000x reference)
#include <cuda_runtime.h>
#include <cuda_fp16.h>
#include <math.h>
#include <stdint.h>

#define B_ 2
#define N_ 4096
#define E_ 1024
#define R_ 128
#define H_ 8
#define ROWS_ (B_*N_)   // 8192
#define CH_ 16          // GLA staging depth

// ---------------- scratch (static device allocations; no cudaMalloc) -------
__device__ float  g_q   [ROWS_*E_];
__device__ float  g_k   [ROWS_*E_];
__device__ float  g_o   [ROWS_*E_];
__device__ float  g_fg  [B_*H_*N_];
__device__ __half g_betah[ROWS_*E_];
__device__ __half g_vh  [ROWS_*E_];
__device__ __half g_gateh[ROWS_*E_];
__device__ __half g_xh  [ROWS_*E_];
__device__ __half g_uh  [ROWS_*R_];
__device__ __half g_u2h [ROWS_*R_];
__device__ __half g_t2h [ROWS_*E_];
__device__ __half g_wqh [E_*E_];
__device__ __half g_wkh [E_*E_];
__device__ __half g_wvh [E_*E_];
__device__ __half g_woh [E_*E_];
__device__ __half g_wb1h[R_*E_];
__device__ __half g_wb2h[E_*R_];
__device__ __half g_wg1h[R_*E_];
__device__ __half g_wg2h[E_*R_];

// ---------------- helpers ----------------------------------------------------
__device__ __forceinline__ float act_rt(float x, int a) {
    if (a == 1) return x * (1.f / (1.f + __expf(-x)));   // silu
    if (a == 2) return 1.f / (1.f + __expf(-x));          // sigmoid
    return x;
}

__device__ __forceinline__ void mma_f16(float c[4], const uint32_t a[4], const uint32_t b[2]) {
    asm volatile(
        "mma.sync.aligned.m16n8k16.row.col.f32.f16.f16.f32 "
        "{%0,%1,%2,%3}, {%4,%5,%6,%7}, {%8,%9}, {%0,%1,%2,%3};"
        : "+f"(c[0]), "+f"(c[1]), "+f"(c[2]), "+f"(c[3])
        : "r"(a[0]), "r"(a[1]), "r"(a[2]), "r"(a[3]), "r"(b[0]), "r"(b[1]));
}

__device__ __forceinline__ void ldsm4(uint32_t& r0, uint32_t& r1, uint32_t& r2, uint32_t& r3,
                                      uint32_t saddr) {
    asm volatile("ldmatrix.sync.aligned.m8n8.x4.shared.b16 {%0,%1,%2,%3}, [%4];"
        : "=r"(r0), "=r"(r1), "=r"(r2), "=r"(r3) : "r"(saddr));
}

__device__ __forceinline__ void cp16(void* smem, const void* gmem) {
    uint32_t s = (uint32_t)__cvta_generic_to_shared(smem);
    asm volatile("cp.async.cg.shared.global [%0], [%1], 16;" :: "r"(s), "l"(gmem));
}
__device__ __forceinline__ void cp16u(uint32_t saddr, const void* gmem) {
    asm volatile("cp.async.cg.shared.global [%0], [%1], 16;" :: "r"(saddr), "l"(gmem));
}

// ---------------- fused fp32 -> fp16 conversion (one launch) ----------------
struct ConvB {
    const float* src[9];
    __half*      dst[9];
    int          boff[10];
};
__global__ void conv_all(ConvB cb)
{
    const int b = blockIdx.x;
    int s = 0;
#pragma unroll
    for (int i = 0; i < 8; i++) if (b >= cb.boff[i + 1]) s = i + 1;
    const int local = b - cb.boff[s];
    const int i = local * 2048 + threadIdx.x * 8;
    const float4 a = *reinterpret_cast<const float4*>(cb.src[s] + i);
    const float4 c = *reinterpret_cast<const float4*>(cb.src[s] + i + 4);
    __half2 h[4];
    h[0] = __floats2half2_rn(a.x, a.y); h[1] = __floats2half2_rn(a.z, a.w);
    h[2] = __floats2half2_rn(c.x, c.y); h[3] = __floats2half2_rn(c.z, c.w);
    *reinterpret_cast<uint4*>(cb.dst[s] + i) = *reinterpret_cast<uint4*>(h);
}

// ---------------- fp16 tensor-core NT GEMM (flat grid, per-z dims) ----------
struct GB5 {
    const __half* A[5];
    const __half* W[5];
    void*         C[5];
    int act[5], oh[5], Nc[5], K[5], bnmax[5];
    int cum[6];     // cumulative block offsets per z
};
#define LDSH 72
#define STAGE_B (128 * LDSH * 2)
#define NSTG 2
#define GEMM_SMEM (2 * NSTG * STAGE_B)  // 73728
__global__ void __launch_bounds__(256, 2) gemm_fp16(GB5 gb)
{
    extern __shared__ char hsm[];
    const uint32_t sA = (uint32_t)__cvta_generic_to_shared(hsm);
    const uint32_t sW = sA + NSTG * STAGE_B;

    const int id = blockIdx.x;
    int z = 0;
#pragma unroll
    for (int i = 0; i < 4; i++) if (id >= gb.cum[i + 1]) z = i + 1;
    const int local = id - gb.cum[z];
    const int bn = local % gb.bnmax[z];
    const int bm = local / gb.bnmax[z];

    const __half* __restrict__ A = gb.A[z];
    const __half* __restrict__ W = gb.W[z];
    void* Cv = gb.C[z];
    const int ACT = gb.act[z];
    const int OH  = gb.oh[z];
    const int Nc  = gb.Nc[z];
    const int K   = gb.K[z];

    const int t    = threadIdx.x;
    const int warp = t >> 5, lane = t & 31;
    const int wm = (warp >> 1) * 32;
    const int wn = (warp & 1) * 64;
    const int gm = lane >> 2, gc = lane & 3;

    float acc[2][8][4];
#pragma unroll
    for (int i = 0; i < 2; i++)
#pragma unroll
        for (int j = 0; j < 8; j++)
#pragma unroll
            for (int l = 0; l < 4; l++) acc[i][j][l] = 0.f;

    const int row  = t >> 1;
    const int half = t & 1;
    const __half* Ap = A + (size_t)(bm * 128 + row) * K + half * 32;
    const __half* Wp = W + (size_t)(bn * 128 + row) * K + half * 32;
    const uint32_t stOff = (uint32_t)(row * LDSH + half * 32) * 2u;

    const int nc = K >> 6;
    auto issue = [&](int s) {
        if (s < nc) {
            const uint32_t st = (uint32_t)(s & (NSTG - 1));
            const uint32_t ab = sA + st * STAGE_B + stOff;
            const uint32_t wb = sW + st * STAGE_B + stOff;
            const __half* Ag = Ap + s * 64;
            const __half* Wg = Wp + s * 64;
#pragma unroll
            for (int j = 0; j < 4; j++) {
                cp16u(ab + j * 16u, Ag + j * 8);
                cp16u(wb + j * 16u, Wg + j * 8);
            }
            asm volatile("cp.async.commit_group;" ::: "memory");
        }
    };

    issue(0);

    const int aRow = wm + (lane & 15);
    const int aCol = (lane >> 4) * 8;
    const int bRow = wn + ((lane >> 4) << 3) + (lane & 7);
    const int bCol = ((lane >> 3) & 1) * 8;

    for (int i = 0; i < nc; i++) {
        asm volatile("cp.async.wait_group 0;" ::: "memory");
        __syncthreads();
        issue(i + 1);
        const uint32_t st = (uint32_t)(i & (NSTG - 1));
        const uint32_t aBuf = sA + st * STAGE_B;
        const uint32_t wBuf = sW + st * STAGE_B;
#pragma unroll
        for (int ks = 0; ks < 64; ks += 16) {
            uint32_t af[2][4];
#pragma unroll
            for (int mt = 0; mt < 2; mt++)
                ldsm4(af[mt][0], af[mt][1], af[mt][2], af[mt][3],
                      aBuf + (uint32_t)((aRow + mt * 16) * LDSH + aCol + ks) * 2u);
            uint32_t bf[8][2];
#pragma unroll
            for (int p = 0; p < 4; p++) {
                uint32_t r0, r1, r2, r3;
                ldsm4(r0, r1, r2, r3,
                      wBuf + (uint32_t)((bRow + p * 16) * LDSH + bCol + ks) * 2u);
                bf[2*p][0]   = r0; bf[2*p][1]   = r1;
                bf[2*p+1][0] = r2; bf[2*p+1][1] = r3;
            }
#pragma unroll
            for (int mt = 0; mt < 2; mt++)
#pragma unroll
                for (int nt = 0; nt < 8; nt++)
                    mma_f16(acc[mt][nt], af[mt], bf[nt]);
        }
    }

#pragma unroll
    for (int mt = 0; mt < 2; mt++) {
        const int row0 = bm * 128 + wm + mt * 16 + gm;
#pragma unroll
        for (int nt = 0; nt < 8; nt++) {
            const int col = bn * 128 + wn + nt * 8 + 2 * gc;
            float v0 = act_rt(acc[mt][nt][0], ACT), v1 = act_rt(acc[mt][nt][1], ACT);
            float v2 = act_rt(acc[mt][nt][2], ACT), v3 = act_rt(acc[mt][nt][3], ACT);
            if (OH) {
                __half* Ch = (__half*)Cv;
                *reinterpret_cast<__half2*>(Ch + (size_t)row0 * Nc + col) =
                    __floats2half2_rn(v0, v1);
                *reinterpret_cast<__half2*>(Ch + (size_t)(row0 + 8) * Nc + col) =
                    __floats2half2_rn(v2, v3);
            } else {
                float* Cf = (float*)Cv;
                *reinterpret_cast<float2*>(Cf + (size_t)row0 * Nc + col)       = make_float2(v0, v1);
                *reinterpret_cast<float2*>(Cf + (size_t)(row0 + 8) * Nc + col) = make_float2(v2, v3);
            }
        }
    }
}

// ---------------- f projection + decay gate (fp16 x) ------------------------
__global__ void fdecay_kernel(const __half* __restrict__ x, const float* __restrict__ Wf,
                              const float* __restrict__ llb, float* __restrict__ fgout)
{
    const int row  = blockIdx.x;
    const int h    = threadIdx.x >> 5;
    const int lane = threadIdx.x & 31;
    const __half* xr = x  + (size_t)row * E_;
    const float*  wr = Wf + (size_t)h   * E_;
    float s = 0.f;
    for (int e = lane * 2; e < E_; e += 64) {
        const float2 xv = __half22float2(*reinterpret_cast<const __half2*>(xr + e));
        s = fmaf(xv.x, wr[e], s);
        s = fmaf(xv.y, wr[e + 1], s);
    }
#pragma unroll
    for (int m = 16; m; m >>= 1) s += __shfl_xor_sync(0xffffffffu, s, m);
    if (lane == 0) {
        const float lb  = __expf(llb[h]);
        const float fgv = lb + (1.f - lb) * (1.f / (1.f + __expf(-s)));
        const int b = row >> 12;
        const int n = row & (N_ - 1);
        fgout[((size_t)b * H_ + h) * N_ + n] = fgv;
    }
}

// ---------------- householder (fp32 q, fp16 beta; fp32 math) ----------------
__global__ void householder_kernel(float* __restrict__ q, const __half* __restrict__ beta)
{
    const int row = blockIdx.x, t = threadIdx.x;
    const size_t base = (size_t)row * E_ + t * 4;
    const uint2 br = *reinterpret_cast<const uint2*>(beta + base);
    const float2 b01 = __half22float2(*reinterpret_cast<const __half2*>(&br.x));
    const float2 b23 = __half22float2(*reinterpret_cast<const __half2*>(&br.y));
    float4 q4 = *reinterpret_cast<float4*>(q + base);
    float ss = b01.x * b01.x + b01.y * b01.y + b23.x * b23.x + b23.y * b23.y;
    float dq = q4.x * b01.x + q4.y * b01.y + q4.z * b23.x + q4.w * b23.y;
#pragma unroll
    for (int m = 16; m; m >>= 1) {
        ss += __shfl_xor_sync(0xffffffffu, ss, m);
        dq += __shfl_xor_sync(0xffffffffu, dq, m);
    }
    __shared__ float sred[2][8];
    const int w = t >> 5, lane = t & 31;
    if (lane == 0) { sred[0][w] = ss; sred[1][w] = dq; }
    __syncthreads();
    float sst = 0.f, dqt = 0.f;
#pragma unroll
    for (int i = 0; i < 8; i++) { sst += sred[0][i]; dqt += sred[1][i]; }
    const float coef = 2.f * dqt / (sst + 1e-12f);
    q4.x -= coef * b01.x; q4.y -= coef * b01.y;
    q4.z -= coef * b23.x; q4.w -= coef * b23.y;
    *reinterpret_cast<float4*>(q + base) = q4;
}

// ---------------- GLA recurrence (fp32 q/k, fp16 v; R9-proven loop) ---------
// 16 v-splits per (b,h): grid 256. block: 8 cols x 16 thr, S[8]/thread.
__global__ void __launch_bounds__(128) gla_kernel(
    const float* __restrict__ q, const float* __restrict__ k,
    const __half* __restrict__ v, const float* __restrict__ fg,
    float* __restrict__ o)
{
    const int bid = blockIdx.x;
    const int vg  = bid & 15;
    const int bh  = bid >> 4;
    const int b   = bh >> 3, h = bh & 7;
    const int t   = threadIdx.x;
    const int col = t >> 4, kg = t & 15;

    __shared__ alignas(16) float  sk[2][CH_][128];
    __shared__ alignas(16) float  sq[2][CH_][128];
    __shared__ alignas(16) __half sv[2][CH_][8];
    __shared__ alignas(16) float  sg[2][CH_];

    const size_t rowbase = (size_t)b * N_ * E_ + (size_t)h * R_;
    const float*  kb  = k + rowbase;
    const float*  qb  = q + rowbase;
    const __half* vb  = v + rowbase + vg * 8;
    const float*  fgb = fg + (size_t)bh * N_;
    float* ob = o + rowbase + vg * 8 + col;

    auto issue_stage = [&](int st, int n0) {
#pragma unroll
        for (int c = 0; c < 4; c++) {
            const int idx  = c * 128 + t;      // 0..511
            const int step = idx >> 5;          // 0..15
            const int part = idx & 31;          // float4 index within row
            cp16(&sk[st][step][part * 4], kb + (size_t)(n0 + step) * E_ + part * 4);
            cp16(&sq[st][step][part * 4], qb + (size_t)(n0 + step) * E_ + part * 4);
        }
        if (t < 16)                             // v: 8 halves = 16B per step
            cp16(&sv[st][t][0], vb + (size_t)(n0 + t) * E_);
        if (t < 4)
            cp16(&sg[st][t * 4], fgb + n0 + t * 4);
    };

    float S[8];
#pragma unroll
    for (int i = 0; i < 8; i++) S[i] = 0.f;

    issue_stage(0, 0);
    asm volatile("cp.async.commit_group;" ::: "memory");

    const float scale = rsqrtf((float)R_);
    for (int blk = 0; blk < N_ / CH_; blk++) {
        const int cur = blk & 1, nxt = cur ^ 1;
        if (blk + 1 < N_ / CH_) issue_stage(nxt, (blk + 1) * CH_);
        asm volatile("cp.async.commit_group;" ::: "memory");
        asm volatile("cp.async.wait_group 1;" ::: "memory");
        __syncthreads();
#pragma unroll 4
        for (int s = 0; s < CH_; s++) {
            const float eg   = sg[cur][s];
            const float vval = __half2float(sv[cur][s][col]);
            const float4 k4a = *reinterpret_cast<const float4*>(&sk[cur][s][kg * 8]);
            const float4 q4a = *reinterpret_cast<const float4*>(&sq[cur][s][kg * 8]);
            const float4 k4b = *reinterpret_cast<const float4*>(&sk[cur][s][kg * 8 + 4]);
            const float4 q4b = *reinterpret_cast<const float4*>(&sq[cur][s][kg * 8 + 4]);
            float a0 = 0.f, a1 = 0.f;
            S[0] = fmaf(S[0], eg, k4a.x * vval); a0 = fmaf(q4a.x, S[0], a0);
            S[1] = fmaf(S[1], eg, k4a.y * vval); a0 = fmaf(q4a.y, S[1], a0);
            S[2] = fmaf(S[2], eg, k4a.z * vval); a0 = fmaf(q4a.z, S[2], a0);
            S[3] = fmaf(S[3], eg, k4a.w * vval); a0 = fmaf(q4a.w, S[3], a0);
            S[4] = fmaf(S[4], eg, k4b.x * vval); a1 = fmaf(q4b.x, S[4], a1);
            S[5] = fmaf(S[5], eg, k4b.y * vval); a1 = fmaf(q4b.y, S[5], a1);
            S[6] = fmaf(S[6], eg, k4b.z * vval); a1 = fmaf(q4b.z, S[6], a1);
            S[7] = fmaf(S[7], eg, k4b.w * vval); a1 = fmaf(q4b.w, S[7], a1);
            float acc = a0 + a1;
            acc += __shfl_xor_sync(0xffffffffu, acc, 1);
            acc += __shfl_xor_sync(0xffffffffu, acc, 2);
            acc += __shfl_xor_sync(0xffffffffu, acc, 4);
            acc += __shfl_xor_sync(0xffffffffu, acc, 8);
            if (kg == 0) ob[(size_t)(blk * CH_ + s) * E_] = acc * scale;
        }
        __syncthreads();
    }
}

// ---------------- gate(fp16) * o(fp32), LayerNorm, write fp16 ---------------
__global__ void gateln_kernel(const float* __restrict__ o, const __half* __restrict__ gate,
                              const float* __restrict__ gamma, __half* __restrict__ out)
{
    const int row = blockIdx.x, t = threadIdx.x;
    const size_t base = (size_t)row * E_ + t * 4;
    float4 ov = *reinterpret_cast<const float4*>(o + base);
    const uint2 gr = *reinterpret_cast<const uint2*>(gate + base);
    const float2 g01 = __half22float2(*reinterpret_cast<const __half2*>(&gr.x));
    const float2 g23 = __half22float2(*reinterpret_cast<const __half2*>(&gr.y));
    ov.x *= g01.x; ov.y *= g01.y; ov.z *= g23.x; ov.w *= g23.y;
    float s  = ov.x + ov.y + ov.z + ov.w;
    float s2 = ov.x * ov.x + ov.y * ov.y + ov.z * ov.z + ov.w * ov.w;
#pragma unroll
    for (int m = 16; m; m >>= 1) {
        s  += __shfl_xor_sync(0xffffffffu, s,  m);
        s2 += __shfl_xor_sync(0xffffffffu, s2, m);
    }
    __shared__ float sred[2][8];
    const int w = t >> 5, lane = t & 31;
    if (lane == 0) { sred[0][w] = s; sred[1][w] = s2; }
    __syncthreads();
    float st = 0.f, s2t = 0.f;
#pragma unroll
    for (int i = 0; i < 8; i++) { st += sred[0][i]; s2t += sred[1][i]; }
    const float mu  = st * (1.f / E_);
    const float var = s2t * (1.f / E_) - mu * mu;
    const float r   = rsqrtf(var + 1e-5f);
    const float4 gm = *reinterpret_cast<const float4*>(gamma + t * 4);
    __half2 h0 = __floats2half2_rn((ov.x - mu) * r * gm.x, (ov.y - mu) * r * gm.y);
    __half2 h1 = __floats2half2_rn((ov.z - mu) * r * gm.z, (ov.w - mu) * r * gm.w);
    *reinterpret_cast<__half2*>(out + base)     = h0;
    *reinterpret_cast<__half2*>(out + base + 2) = h1;
}

// ---------------- launch ----------------------------------------------------
extern "C" void kernel_launch(void* const* d_in, const int* in_sizes, int n_in,
                              void* d_out, int out_size)
{
    (void)in_sizes; (void)n_in; (void)out_size;
    const float* x   = (const float*)d_in[0];
    const float* llb = (const float*)d_in[1];
    const float* Wq  = (const float*)d_in[2];
    const float* Wk  = (const float*)d_in[3];
    const float* Wv  = (const float*)d_in[4];
    const float* Wf  = (const float*)d_in[5];
    const float* Wb1 = (const float*)d_in[6];
    const float* Wb2 = (const float*)d_in[7];
    const float* Wg1 = (const float*)d_in[8];
    const float* Wg2 = (const float*)d_in[9];
    const float* gamma = (const float*)d_in[10];
    const float* Wo  = (const float*)d_in[11];
    float* out = (float*)d_out;

    float *q, *k, *o, *fg;
    __half *betah, *vh, *gateh, *xh, *uh, *u2h, *t2h;
    __half *wqh, *wkh, *wvh, *woh, *wb1h, *wb2h, *wg1h, *wg2h;
    cudaGetSymbolAddress((void**)&q,    g_q);
    cudaGetSymbolAddress((void**)&k,    g_k);
    cudaGetSymbolAddress((void**)&o,    g_o);
    cudaGetSymbolAddress((void**)&fg,   g_fg);
    cudaGetSymbolAddress((void**)&betah,g_betah);
    cudaGetSymbolAddress((void**)&vh,   g_vh);
    cudaGetSymbolAddress((void**)&gateh,g_gateh);
    cudaGetSymbolAddress((void**)&xh,   g_xh);
    cudaGetSymbolAddress((void**)&uh,   g_uh);
    cudaGetSymbolAddress((void**)&u2h,  g_u2h);
    cudaGetSymbolAddress((void**)&t2h,  g_t2h);
    cudaGetSymbolAddress((void**)&wqh,  g_wqh);
    cudaGetSymbolAddress((void**)&wkh,  g_wkh);
    cudaGetSymbolAddress((void**)&wvh,  g_wvh);
    cudaGetSymbolAddress((void**)&woh,  g_woh);
    cudaGetSymbolAddress((void**)&wb1h, g_wb1h);
    cudaGetSymbolAddress((void**)&wb2h, g_wb2h);
    cudaGetSymbolAddress((void**)&wg1h, g_wg1h);
    cudaGetSymbolAddress((void**)&wg2h, g_wg2h);

    cudaFuncSetAttribute(gemm_fp16, cudaFuncAttributeMaxDynamicSharedMemorySize, GEMM_SMEM);

    // one fused conversion launch (x + 8 weight matrices)
    {
        ConvB cb{};
        const float* srcs[9] = {x, Wq, Wk, Wv, Wo, Wb1, Wb2, Wg1, Wg2};
        __half* dsts[9] = {xh, wqh, wkh, wvh, woh, wb1h, wb2h, wg1h, wg2h};
        const int ns[9] = {ROWS_*E_, E_*E_, E_*E_, E_*E_, E_*E_,
                           R_*E_, E_*R_, R_*E_, E_*R_};
        int off = 0;
        for (int i = 0; i < 9; i++) {
            cb.src[i] = srcs[i]; cb.dst[i] = dsts[i];
            cb.boff[i] = off; off += ns[i] / 2048;
        }
        cb.boff[9] = off;
        conv_all<<<off, 256>>>(cb);
    }

    const dim3 blk(256);

    // mega GEMM: q,k fp32 out (z0,1), v fp16 (z2), low-rank u/u2 (z3,4). Flat grid.
    {
        GB5 gb{};
        gb.A[0] = xh; gb.W[0] = wqh;  gb.C[0] = q;    gb.act[0] = 1; gb.oh[0] = 0; gb.Nc[0] = E_; gb.K[0] = E_; gb.bnmax[0] = 8;
        gb.A[1] = xh; gb.W[1] = wkh;  gb.C[1] = k;    gb.act[1] = 1; gb.oh[1] = 0; gb.Nc[1] = E_; gb.K[1] = E_; gb.bnmax[1] = 8;
        gb.A[2] = xh; gb.W[2] = wvh;  gb.C[2] = vh;   gb.act[2] = 0; gb.oh[2] = 1; gb.Nc[2] = E_; gb.K[2] = E_; gb.bnmax[2] = 8;
        gb.A[3] = xh; gb.W[3] = wb1h; gb.C[3] = uh;   gb.act[3] = 0; gb.oh[3] = 1; gb.Nc[3] = R_; gb.K[3] = E_; gb.bnmax[3] = 1;
        gb.A[4] = xh; gb.W[4] = wg1h; gb.C[4] = u2h;  gb.act[4] = 0; gb.oh[4] = 1; gb.Nc[4] = R_; gb.K[4] = E_; gb.bnmax[4] = 1;
        gb.cum[0] = 0;    gb.cum[1] = 512;  gb.cum[2] = 1024;
        gb.cum[3] = 1536; gb.cum[4] = 1600; gb.cum[5] = 1664;
        gemm_fp16<<<1664, blk, GEMM_SMEM>>>(gb);
    }

    fdecay_kernel<<<ROWS_, 256>>>(xh, Wf, llb, fg);

    // beta = silu(u Wb2^T) fp16, gate = sigmoid(u2 Wg2^T) fp16
    {
        GB5 gb{};
        gb.A[0] = uh;  gb.W[0] = wb2h; gb.C[0] = betah; gb.act[0] = 1; gb.oh[0] = 1; gb.Nc[0] = E_; gb.K[0] = R_; gb.bnmax[0] = 8;
        gb.A[1] = u2h; gb.W[1] = wg2h; gb.C[1] = gateh; gb.act[1] = 2; gb.oh[1] = 1; gb.Nc[1] = E_; gb.K[1] = R_; gb.bnmax[1] = 8;
        gb.cum[0] = 0; gb.cum[1] = 512; gb.cum[2] = 1024;
        gb.cum[3] = 1024; gb.cum[4] = 1024; gb.cum[5] = 1024;
        gemm_fp16<<<1024, blk, GEMM_SMEM>>>(gb);
    }

    householder_kernel<<<ROWS_, 256>>>(q, betah);

    gla_kernel<<<B_ * H_ * 16, 128>>>(q, k, vh, fg, o);

    gateln_kernel<<<ROWS_, 256>>>(o, gateh, gamma, t2h);

    // output projection (fp32 out)
    {
        GB5 gb{};
        gb.A[0] = t2h; gb.W[0] = woh; gb.C[0] = out; gb.act[0] = 0; gb.oh[0] = 0; gb.Nc[0] = E_; gb.K[0] = E_; gb.bnmax[0] = 8;
        gb.cum[0] = 0; gb.cum[1] = 512; gb.cum[2] = 512;
        gb.cum[3] = 512; gb.cum[4] = 512; gb.cum[5] = 512;
        gemm_fp16<<<512, blk, GEMM_SMEM>>>(gb);
    }
}

// round 14
// speedup vs baseline: 1.4853x; 1.4853x over previous
#include <cuda_runtime.h>
#include <cuda_fp16.h>
#include <math.h>
#include <stdint.h>

#define B_ 2
#define N_ 4096
#define E_ 1024
#define R_ 128
#define H_ 8
#define ROWS_ (B_*N_)   // 8192
#define CH_ 32          // GLA staging depth (steps per smem stage)

// ---------------- scratch (static device allocations; no cudaMalloc) -------
__device__ float  g_o   [ROWS_*E_];
__device__ float  g_fg  [B_*H_*N_];
__device__ __half g_betah[ROWS_*E_];
__device__ __half g_qh  [ROWS_*E_];
__device__ __half g_kh  [ROWS_*E_];
__device__ __half g_vh  [ROWS_*E_];
__device__ __half g_gateh[ROWS_*E_];
__device__ __half g_xh  [ROWS_*E_];
__device__ __half g_uh  [ROWS_*R_];
__device__ __half g_u2h [ROWS_*R_];
__device__ __half g_t2h [ROWS_*E_];
__device__ __half g_wqh [E_*E_];
__device__ __half g_wkh [E_*E_];
__device__ __half g_wvh [E_*E_];
__device__ __half g_woh [E_*E_];
__device__ __half g_wb1h[R_*E_];
__device__ __half g_wb2h[E_*R_];
__device__ __half g_wg1h[R_*E_];
__device__ __half g_wg2h[E_*R_];

// ---------------- helpers ----------------------------------------------------
__device__ __forceinline__ float act_rt(float x, int a) {
    if (a == 1) return x * (1.f / (1.f + __expf(-x)));   // silu
    if (a == 2) return 1.f / (1.f + __expf(-x));          // sigmoid
    return x;
}

__device__ __forceinline__ void mma_f16(float c[4], const uint32_t a[4], const uint32_t b[2]) {
    asm volatile(
        "mma.sync.aligned.m16n8k16.row.col.f32.f16.f16.f32 "
        "{%0,%1,%2,%3}, {%4,%5,%6,%7}, {%8,%9}, {%0,%1,%2,%3};"
        : "+f"(c[0]), "+f"(c[1]), "+f"(c[2]), "+f"(c[3])
        : "r"(a[0]), "r"(a[1]), "r"(a[2]), "r"(a[3]), "r"(b[0]), "r"(b[1]));
}

__device__ __forceinline__ void ldsm4(uint32_t& r0, uint32_t& r1, uint32_t& r2, uint32_t& r3,
                                      uint32_t saddr) {
    asm volatile("ldmatrix.sync.aligned.m8n8.x4.shared.b16 {%0,%1,%2,%3}, [%4];"
        : "=r"(r0), "=r"(r1), "=r"(r2), "=r"(r3) : "r"(saddr));
}

__device__ __forceinline__ void cp16(void* smem, const void* gmem) {
    uint32_t s = (uint32_t)__cvta_generic_to_shared(smem);
    asm volatile("cp.async.cg.shared.global [%0], [%1], 16;" :: "r"(s), "l"(gmem));
}
__device__ __forceinline__ void cp16u(uint32_t saddr, const void* gmem) {
    asm volatile("cp.async.cg.shared.global [%0], [%1], 16;" :: "r"(saddr), "l"(gmem));
}

// ---------------- fused fp32 -> fp16 conversion (one launch) ----------------
struct ConvB {
    const float* src[9];
    __half*      dst[9];
    int          boff[10];
};
__global__ void conv_all(ConvB cb)
{
    const int b = blockIdx.x;
    int s = 0;
#pragma unroll
    for (int i = 0; i < 8; i++) if (b >= cb.boff[i + 1]) s = i + 1;
    const int local = b - cb.boff[s];
    const int i = local * 2048 + threadIdx.x * 8;
    const float4 a = *reinterpret_cast<const float4*>(cb.src[s] + i);
    const float4 c = *reinterpret_cast<const float4*>(cb.src[s] + i + 4);
    __half2 h[4];
    h[0] = __floats2half2_rn(a.x, a.y); h[1] = __floats2half2_rn(a.z, a.w);
    h[2] = __floats2half2_rn(c.x, c.y); h[3] = __floats2half2_rn(c.z, c.w);
    *reinterpret_cast<uint4*>(cb.dst[s] + i) = *reinterpret_cast<uint4*>(h);
}

// ---------------- fp16 tensor-core NT GEMM (batched, per-z dims) ------------
struct GB5 {
    const __half* A[5];
    const __half* W[5];
    void*         C[5];
    int act[5], oh[5], Nc[5], K[5], bnmax[5];
};
#define LDSH 72
#define STAGE_B (128 * LDSH * 2)
#define NSTG 2
#define GEMM_SMEM (2 * NSTG * STAGE_B)  // 73728
__global__ void __launch_bounds__(256, 2) gemm_fp16(GB5 gb)
{
    extern __shared__ char hsm[];
    const uint32_t sA = (uint32_t)__cvta_generic_to_shared(hsm);
    const uint32_t sW = sA + NSTG * STAGE_B;

    const int z  = blockIdx.z;
    const int bm = blockIdx.y, bn = blockIdx.x;
    if (bn >= gb.bnmax[z]) return;
    const __half* __restrict__ A = gb.A[z];
    const __half* __restrict__ W = gb.W[z];
    void* Cv = gb.C[z];
    const int ACT = gb.act[z];
    const int OH  = gb.oh[z];
    const int Nc  = gb.Nc[z];
    const int K   = gb.K[z];

    const int t    = threadIdx.x;
    const int warp = t >> 5, lane = t & 31;
    const int wm = (warp >> 1) * 32;
    const int wn = (warp & 1) * 64;
    const int gm = lane >> 2, gc = lane & 3;

    float acc[2][8][4];
#pragma unroll
    for (int i = 0; i < 2; i++)
#pragma unroll
        for (int j = 0; j < 8; j++)
#pragma unroll
            for (int l = 0; l < 4; l++) acc[i][j][l] = 0.f;

    const int row  = t >> 1;
    const int half = t & 1;
    const __half* Ap = A + (size_t)(bm * 128 + row) * K + half * 32;
    const __half* Wp = W + (size_t)(bn * 128 + row) * K + half * 32;
    const uint32_t stOff = (uint32_t)(row * LDSH + half * 32) * 2u;

    const int nc = K >> 6;
    auto issue = [&](int s) {
        if (s < nc) {
            const uint32_t st = (uint32_t)(s & (NSTG - 1));
            const uint32_t ab = sA + st * STAGE_B + stOff;
            const uint32_t wb = sW + st * STAGE_B + stOff;
            const __half* Ag = Ap + s * 64;
            const __half* Wg = Wp + s * 64;
#pragma unroll
            for (int j = 0; j < 4; j++) {
                cp16u(ab + j * 16u, Ag + j * 8);
                cp16u(wb + j * 16u, Wg + j * 8);
            }
            asm volatile("cp.async.commit_group;" ::: "memory");
        }
    };

    issue(0);

    const int aRow = wm + (lane & 15);
    const int aCol = (lane >> 4) * 8;
    const int bRow = wn + ((lane >> 4) << 3) + (lane & 7);
    const int bCol = ((lane >> 3) & 1) * 8;

    for (int i = 0; i < nc; i++) {
        asm volatile("cp.async.wait_group 0;" ::: "memory");
        __syncthreads();
        issue(i + 1);
        const uint32_t st = (uint32_t)(i & (NSTG - 1));
        const uint32_t aBuf = sA + st * STAGE_B;
        const uint32_t wBuf = sW + st * STAGE_B;
#pragma unroll
        for (int ks = 0; ks < 64; ks += 16) {
            uint32_t af[2][4];
#pragma unroll
            for (int mt = 0; mt < 2; mt++)
                ldsm4(af[mt][0], af[mt][1], af[mt][2], af[mt][3],
                      aBuf + (uint32_t)((aRow + mt * 16) * LDSH + aCol + ks) * 2u);
            uint32_t bf[8][2];
#pragma unroll
            for (int p = 0; p < 4; p++) {
                uint32_t r0, r1, r2, r3;
                ldsm4(r0, r1, r2, r3,
                      wBuf + (uint32_t)((bRow + p * 16) * LDSH + bCol + ks) * 2u);
                bf[2*p][0]   = r0; bf[2*p][1]   = r1;
                bf[2*p+1][0] = r2; bf[2*p+1][1] = r3;
            }
#pragma unroll
            for (int mt = 0; mt < 2; mt++)
#pragma unroll
                for (int nt = 0; nt < 8; nt++)
                    mma_f16(acc[mt][nt], af[mt], bf[nt]);
        }
    }

#pragma unroll
    for (int mt = 0; mt < 2; mt++) {
        const int row0 = bm * 128 + wm + mt * 16 + gm;
#pragma unroll
        for (int nt = 0; nt < 8; nt++) {
            const int col = bn * 128 + wn + nt * 8 + 2 * gc;
            float v0 = act_rt(acc[mt][nt][0], ACT), v1 = act_rt(acc[mt][nt][1], ACT);
            float v2 = act_rt(acc[mt][nt][2], ACT), v3 = act_rt(acc[mt][nt][3], ACT);
            if (OH) {
                __half* Ch = (__half*)Cv;
                *reinterpret_cast<__half2*>(Ch + (size_t)row0 * Nc + col) =
                    __floats2half2_rn(v0, v1);
                *reinterpret_cast<__half2*>(Ch + (size_t)(row0 + 8) * Nc + col) =
                    __floats2half2_rn(v2, v3);
            } else {
                float* Cf = (float*)Cv;
                *reinterpret_cast<float2*>(Cf + (size_t)row0 * Nc + col)       = make_float2(v0, v1);
                *reinterpret_cast<float2*>(Cf + (size_t)(row0 + 8) * Nc + col) = make_float2(v2, v3);
            }
        }
    }
}

// ---------------- f projection + decay gate (fp16 x) ------------------------
__global__ void fdecay_kernel(const __half* __restrict__ x, const float* __restrict__ Wf,
                              const float* __restrict__ llb, float* __restrict__ fgout)
{
    const int row  = blockIdx.x;
    const int h    = threadIdx.x >> 5;
    const int lane = threadIdx.x & 31;
    const __half* xr = x  + (size_t)row * E_;
    const float*  wr = Wf + (size_t)h   * E_;
    float s = 0.f;
    for (int e = lane * 2; e < E_; e += 64) {
        const float2 xv = __half22float2(*reinterpret_cast<const __half2*>(xr + e));
        s = fmaf(xv.x, wr[e], s);
        s = fmaf(xv.y, wr[e + 1], s);
    }
#pragma unroll
    for (int m = 16; m; m >>= 1) s += __shfl_xor_sync(0xffffffffu, s, m);
    if (lane == 0) {
        const float lb  = __expf(llb[h]);
        const float fgv = lb + (1.f - lb) * (1.f / (1.f + __expf(-s)));
        const int b = row >> 12;
        const int n = row & (N_ - 1);
        fgout[((size_t)b * H_ + h) * N_ + n] = fgv;
    }
}

// ---------------- householder (fp16 q, fp16 beta; fp32 math) ----------------
__global__ void householder_kernel(__half* __restrict__ q, const __half* __restrict__ beta)
{
    const int row = blockIdx.x, t = threadIdx.x;
    const size_t base = (size_t)row * E_ + t * 4;
    const uint2 br = *reinterpret_cast<const uint2*>(beta + base);
    const float2 b01 = __half22float2(*reinterpret_cast<const __half2*>(&br.x));
    const float2 b23 = __half22float2(*reinterpret_cast<const __half2*>(&br.y));
    uint2 qr = *reinterpret_cast<uint2*>(q + base);
    float2 q01 = __half22float2(*reinterpret_cast<__half2*>(&qr.x));
    float2 q23 = __half22float2(*reinterpret_cast<__half2*>(&qr.y));
    float ss = b01.x * b01.x + b01.y * b01.y + b23.x * b23.x + b23.y * b23.y;
    float dq = q01.x * b01.x + q01.y * b01.y + q23.x * b23.x + q23.y * b23.y;
#pragma unroll
    for (int m = 16; m; m >>= 1) {
        ss += __shfl_xor_sync(0xffffffffu, ss, m);
        dq += __shfl_xor_sync(0xffffffffu, dq, m);
    }
    __shared__ float sred[2][8];
    const int w = t >> 5, lane = t & 31;
    if (lane == 0) { sred[0][w] = ss; sred[1][w] = dq; }
    __syncthreads();
    float sst = 0.f, dqt = 0.f;
#pragma unroll
    for (int i = 0; i < 8; i++) { sst += sred[0][i]; dqt += sred[1][i]; }
    const float coef = 2.f * dqt / (sst + 1e-12f);
    __half2 h0 = __floats2half2_rn(q01.x - coef * b01.x, q01.y - coef * b01.y);
    __half2 h1 = __floats2half2_rn(q23.x - coef * b23.x, q23.y - coef * b23.y);
    uint2 out;
    out.x = *reinterpret_cast<uint32_t*>(&h0);
    out.y = *reinterpret_cast<uint32_t*>(&h1);
    *reinterpret_cast<uint2*>(q + base) = out;
}

// ---------------- GLA recurrence (fp16 inputs, 32-step staged) --------------
// 16 v-splits per (b,h): grid 256. block: 8 cols x 16 thr, S[8]/thread.
__global__ void __launch_bounds__(128) gla_kernel(
    const __half* __restrict__ q, const __half* __restrict__ k,
    const __half* __restrict__ v, const float* __restrict__ fg,
    float* __restrict__ o)
{
    const int bid = blockIdx.x;
    const int vg  = bid & 15;
    const int bh  = bid >> 4;
    const int b   = bh >> 3, h = bh & 7;
    const int t   = threadIdx.x;
    const int col = t >> 4, kg = t & 15;

    __shared__ alignas(16) __half sk[2][CH_][128];
    __shared__ alignas(16) __half sq[2][CH_][128];
    __shared__ alignas(16) __half sv[2][CH_][8];
    __shared__ alignas(16) float  sg[2][CH_];

    const size_t rowbase = (size_t)b * N_ * E_ + (size_t)h * R_;
    const __half* kb  = k + rowbase;
    const __half* qb  = q + rowbase;
    const __half* vb  = v + rowbase + vg * 8;
    const float*  fgb = fg + (size_t)bh * N_;
    float* ob = o + rowbase + vg * 8 + col;

    auto issue_stage = [&](int st, int n0) {
#pragma unroll
        for (int c = 0; c < 4; c++) {
            const int idx  = c * 128 + t;     // 0..511
            const int step = idx >> 4;         // 0..31
            const int part = idx & 15;         // 16B chunk = 8 halves
            cp16(&sk[st][step][part * 8], kb + (size_t)(n0 + step) * E_ + part * 8);
            cp16(&sq[st][step][part * 8], qb + (size_t)(n0 + step) * E_ + part * 8);
        }
        if (t < 32)
            cp16(&sv[st][t][0], vb + (size_t)(n0 + t) * E_);
        if (t < 8)
            cp16(&sg[st][t * 4], fgb + n0 + t * 4);
    };

    float S[8];
#pragma unroll
    for (int i = 0; i < 8; i++) S[i] = 0.f;

    issue_stage(0, 0);
    asm volatile("cp.async.commit_group;" ::: "memory");

    const float scale = rsqrtf((float)R_);
    for (int blk = 0; blk < N_ / CH_; blk++) {
        const int cur = blk & 1, nxt = cur ^ 1;
        if (blk + 1 < N_ / CH_) issue_stage(nxt, (blk + 1) * CH_);
        asm volatile("cp.async.commit_group;" ::: "memory");
        asm volatile("cp.async.wait_group 1;" ::: "memory");
        __syncthreads();
#pragma unroll 4
        for (int s = 0; s < CH_; s++) {
            const float eg   = sg[cur][s];
            const float vval = __half2float(sv[cur][s][col]);
            const uint4 kr = *reinterpret_cast<const uint4*>(&sk[cur][s][kg * 8]);
            const uint4 qr = *reinterpret_cast<const uint4*>(&sq[cur][s][kg * 8]);
            const float2 k0 = __half22float2(*reinterpret_cast<const __half2*>(&kr.x));
            const float2 k1 = __half22float2(*reinterpret_cast<const __half2*>(&kr.y));
            const float2 k2 = __half22float2(*reinterpret_cast<const __half2*>(&kr.z));
            const float2 k3 = __half22float2(*reinterpret_cast<const __half2*>(&kr.w));
            const float2 q0 = __half22float2(*reinterpret_cast<const __half2*>(&qr.x));
            const float2 q1 = __half22float2(*reinterpret_cast<const __half2*>(&qr.y));
            const float2 q2 = __half22float2(*reinterpret_cast<const __half2*>(&qr.z));
            const float2 q3 = __half22float2(*reinterpret_cast<const __half2*>(&qr.w));
            float a0 = 0.f, a1 = 0.f;
            S[0] = fmaf(S[0], eg, k0.x * vval); a0 = fmaf(q0.x, S[0], a0);
            S[1] = fmaf(S[1], eg, k0.y * vval); a0 = fmaf(q0.y, S[1], a0);
            S[2] = fmaf(S[2], eg, k1.x * vval); a0 = fmaf(q1.x, S[2], a0);
            S[3] = fmaf(S[3], eg, k1.y * vval); a0 = fmaf(q1.y, S[3], a0);
            S[4] = fmaf(S[4], eg, k2.x * vval); a1 = fmaf(q2.x, S[4], a1);
            S[5] = fmaf(S[5], eg, k2.y * vval); a1 = fmaf(q2.y, S[5], a1);
            S[6] = fmaf(S[6], eg, k3.x * vval); a1 = fmaf(q3.x, S[6], a1);
            S[7] = fmaf(S[7], eg, k3.y * vval); a1 = fmaf(q3.y, S[7], a1);
            float acc = a0 + a1;
            acc += __shfl_xor_sync(0xffffffffu, acc, 1);
            acc += __shfl_xor_sync(0xffffffffu, acc, 2);
            acc += __shfl_xor_sync(0xffffffffu, acc, 4);
            acc += __shfl_xor_sync(0xffffffffu, acc, 8);
            if (kg == 0) ob[(size_t)(blk * CH_ + s) * E_] = acc * scale;
        }
        __syncthreads();
    }
}

// ---------------- gate(fp16) * o(fp32), LayerNorm, write fp16 ---------------
__global__ void gateln_kernel(const float* __restrict__ o, const __half* __restrict__ gate,
                              const float* __restrict__ gamma, __half* __restrict__ out)
{
    const int row = blockIdx.x, t = threadIdx.x;
    const size_t base = (size_t)row * E_ + t * 4;
    float4 ov = *reinterpret_cast<const float4*>(o + base);
    const uint2 gr = *reinterpret_cast<const uint2*>(gate + base);
    const float2 g01 = __half22float2(*reinterpret_cast<const __half2*>(&gr.x));
    const float2 g23 = __half22float2(*reinterpret_cast<const __half2*>(&gr.y));
    ov.x *= g01.x; ov.y *= g01.y; ov.z *= g23.x; ov.w *= g23.y;
    float s  = ov.x + ov.y + ov.z + ov.w;
    float s2 = ov.x * ov.x + ov.y * ov.y + ov.z * ov.z + ov.w * ov.w;
#pragma unroll
    for (int m = 16; m; m >>= 1) {
        s  += __shfl_xor_sync(0xffffffffu, s,  m);
        s2 += __shfl_xor_sync(0xffffffffu, s2, m);
    }
    __shared__ float sred[2][8];
    const int w = t >> 5, lane = t & 31;
    if (lane == 0) { sred[0][w] = s; sred[1][w] = s2; }
    __syncthreads();
    float st = 0.f, s2t = 0.f;
#pragma unroll
    for (int i = 0; i < 8; i++) { st += sred[0][i]; s2t += sred[1][i]; }
    const float mu  = st * (1.f / E_);
    const float var = s2t * (1.f / E_) - mu * mu;
    const float r   = rsqrtf(var + 1e-5f);
    const float4 gm = *reinterpret_cast<const float4*>(gamma + t * 4);
    __half2 h0 = __floats2half2_rn((ov.x - mu) * r * gm.x, (ov.y - mu) * r * gm.y);
    __half2 h1 = __floats2half2_rn((ov.z - mu) * r * gm.z, (ov.w - mu) * r * gm.w);
    *reinterpret_cast<__half2*>(out + base)     = h0;
    *reinterpret_cast<__half2*>(out + base + 2) = h1;
}

// ---------------- launch ----------------------------------------------------
extern "C" void kernel_launch(void* const* d_in, const int* in_sizes, int n_in,
                              void* d_out, int out_size)
{
    (void)in_sizes; (void)n_in; (void)out_size;
    const float* x   = (const float*)d_in[0];
    const float* llb = (const float*)d_in[1];
    const float* Wq  = (const float*)d_in[2];
    const float* Wk  = (const float*)d_in[3];
    const float* Wv  = (const float*)d_in[4];
    const float* Wf  = (const float*)d_in[5];
    const float* Wb1 = (const float*)d_in[6];
    const float* Wb2 = (const float*)d_in[7];
    const float* Wg1 = (const float*)d_in[8];
    const float* Wg2 = (const float*)d_in[9];
    const float* gamma = (const float*)d_in[10];
    const float* Wo  = (const float*)d_in[11];
    float* out = (float*)d_out;

    float *o, *fg;
    __half *betah, *qh, *kh, *vh, *gateh, *xh, *uh, *u2h, *t2h;
    __half *wqh, *wkh, *wvh, *woh, *wb1h, *wb2h, *wg1h, *wg2h;
    cudaGetSymbolAddress((void**)&o,    g_o);
    cudaGetSymbolAddress((void**)&fg,   g_fg);
    cudaGetSymbolAddress((void**)&betah,g_betah);
    cudaGetSymbolAddress((void**)&qh,   g_qh);
    cudaGetSymbolAddress((void**)&kh,   g_kh);
    cudaGetSymbolAddress((void**)&vh,   g_vh);
    cudaGetSymbolAddress((void**)&gateh,g_gateh);
    cudaGetSymbolAddress((void**)&xh,   g_xh);
    cudaGetSymbolAddress((void**)&uh,   g_uh);
    cudaGetSymbolAddress((void**)&u2h,  g_u2h);
    cudaGetSymbolAddress((void**)&t2h,  g_t2h);
    cudaGetSymbolAddress((void**)&wqh,  g_wqh);
    cudaGetSymbolAddress((void**)&wkh,  g_wkh);
    cudaGetSymbolAddress((void**)&wvh,  g_wvh);
    cudaGetSymbolAddress((void**)&woh,  g_woh);
    cudaGetSymbolAddress((void**)&wb1h, g_wb1h);
    cudaGetSymbolAddress((void**)&wb2h, g_wb2h);
    cudaGetSymbolAddress((void**)&wg1h, g_wg1h);
    cudaGetSymbolAddress((void**)&wg2h, g_wg2h);

    cudaFuncSetAttribute(gemm_fp16, cudaFuncAttributeMaxDynamicSharedMemorySize, GEMM_SMEM);

    // one fused conversion launch (x + 8 weight matrices)
    {
        ConvB cb{};
        const float* srcs[9] = {x, Wq, Wk, Wv, Wo, Wb1, Wb2, Wg1, Wg2};
        __half* dsts[9] = {xh, wqh, wkh, wvh, woh, wb1h, wb2h, wg1h, wg2h};
        const int ns[9] = {ROWS_*E_, E_*E_, E_*E_, E_*E_, E_*E_,
                           R_*E_, E_*R_, R_*E_, E_*R_};
        int off = 0;
        for (int i = 0; i < 9; i++) {
            cb.src[i] = srcs[i]; cb.dst[i] = dsts[i];
            cb.boff[i] = off; off += ns[i] / 2048;
        }
        cb.boff[9] = off;
        conv_all<<<off, 256>>>(cb);
    }

    const dim3 blk(256);

    // mega GEMM: qkv (z0-2, fp16 out) + low-rank u/u2 (z3-4)
    {
        GB5 gb{};
        gb.A[0] = xh; gb.W[0] = wqh;  gb.C[0] = qh;   gb.act[0] = 1; gb.oh[0] = 1; gb.Nc[0] = E_; gb.K[0] = E_; gb.bnmax[0] = 8;
        gb.A[1] = xh; gb.W[1] = wkh;  gb.C[1] = kh;   gb.act[1] = 1; gb.oh[1] = 1; gb.Nc[1] = E_; gb.K[1] = E_; gb.bnmax[1] = 8;
        gb.A[2] = xh; gb.W[2] = wvh;  gb.C[2] = vh;   gb.act[2] = 0; gb.oh[2] = 1; gb.Nc[2] = E_; gb.K[2] = E_; gb.bnmax[2] = 8;
        gb.A[3] = xh; gb.W[3] = wb1h; gb.C[3] = uh;   gb.act[3] = 0; gb.oh[3] = 1; gb.Nc[3] = R_; gb.K[3] = E_; gb.bnmax[3] = 1;
        gb.A[4] = xh; gb.W[4] = wg1h; gb.C[4] = u2h;  gb.act[4] = 0; gb.oh[4] = 1; gb.Nc[4] = R_; gb.K[4] = E_; gb.bnmax[4] = 1;
        gemm_fp16<<<dim3(8, ROWS_/128, 5), blk, GEMM_SMEM>>>(gb);
    }

    fdecay_kernel<<<ROWS_, 256>>>(xh, Wf, llb, fg);

    // beta = silu(u Wb2^T) fp16, gate = sigmoid(u2 Wg2^T) fp16
    {
        GB5 gb{};
        gb.A[0] = uh;  gb.W[0] = wb2h; gb.C[0] = betah; gb.act[0] = 1; gb.oh[0] = 1; gb.Nc[0] = E_; gb.K[0] = R_; gb.bnmax[0] = 8;
        gb.A[1] = u2h; gb.W[1] = wg2h; gb.C[1] = gateh; gb.act[1] = 2; gb.oh[1] = 1; gb.Nc[1] = E_; gb.K[1] = R_; gb.bnmax[1] = 8;
        gemm_fp16<<<dim3(8, ROWS_/128, 2), blk, GEMM_SMEM>>>(gb);
    }

    householder_kernel<<<ROWS_, 256>>>(qh, betah);

    gla_kernel<<<B_ * H_ * 16, 128>>>(qh, kh, vh, fg, o);

    gateln_kernel<<<ROWS_, 256>>>(o, gateh, gamma, t2h);

    // output projection (fp32 out)
    {
        GB5 gb{};
        gb.A[0] = t2h; gb.W[0] = woh; gb.C[0] = out; gb.act[0] = 0; gb.oh[0] = 0; gb.Nc[0] = E_; gb.K[0] = E_; gb.bnmax[0] = 8;
        gemm_fp16<<<dim3(8, ROWS_/128, 1), blk, GEMM_SMEM>>>(gb);
    }
}